// round 8
// baseline (speedup 1.0000x reference)
#include <cuda_runtime.h>
#include <math.h>

// ---------------------------------------------------------------------------
// Problem constants
// ---------------------------------------------------------------------------
#define M_Q   16384      // B*T
#define CCTX  4096       // context entries
#define DMOD  512        // D == DC == A == P == 512
#define SCALE_A 0.04419417382415922f   // 1/sqrt(512)

// ---------------------------------------------------------------------------
// Static device scratch (no allocations allowed anywhere)
// ---------------------------------------------------------------------------
__device__ float g_q[(size_t)M_Q * DMOD];       // 32 MB
__device__ float g_k[(size_t)CCTX * DMOD];      //  8 MB
__device__ float g_v[(size_t)CCTX * DMOD];      //  8 MB
__device__ float g_s[(size_t)M_Q * CCTX];       // 256 MB (scores -> attn in place)
__device__ float g_x[(size_t)M_Q * DMOD];       // 32 MB

// ---------------------------------------------------------------------------
// Tiled SGEMM, 128x128 block tile, BK=16, 256 threads, 8x8 per-thread tile
// ---------------------------------------------------------------------------
#define BM 128
#define BN 128
#define BK 16
#define TM 8
#define TNt 8

// C[M,N] = A[M,K] @ B[K,N] (+ bias[N]).  B is row-major [K,N].
__global__ __launch_bounds__(256, 2)
void gemm_nn_bias(const float* __restrict__ A, const float* __restrict__ B,
                  const float* __restrict__ bias, float* __restrict__ C,
                  int M, int N, int K)
{
    __shared__ float As[BK][BM];
    __shared__ float Bs[BK][BN];

    const int bx = blockIdx.x;            // N tile
    const int by = blockIdx.y;            // M tile
    const int tid = threadIdx.x;
    const int tx = tid & 15;              // 0..15  -> 8 cols each
    const int ty = tid >> 4;              // 0..15  -> 8 rows each

    const float* Ablk = A + (size_t)by * BM * K;
    const float* Bblk = B + (size_t)bx * BN;

    // A-tile loader: 128 rows x 16 k, float4 per thread x2
    const int arow = tid >> 2;            // 0..63 (+64)
    const int acol = (tid & 3) * 4;       // k offset
    // B-tile loader: 16 k-rows x 128 n, float4 per thread x2
    const int brow = tid >> 5;            // 0..7 (+8)
    const int bcol = (tid & 31) * 4;      // n offset

    float acc[TM][TNt];
    #pragma unroll
    for (int i = 0; i < TM; i++)
        #pragma unroll
        for (int j = 0; j < TNt; j++) acc[i][j] = 0.0f;

    for (int k0 = 0; k0 < K; k0 += BK) {
        #pragma unroll
        for (int r = 0; r < 2; r++) {
            int row = arow + r * 64;
            float4 a = *(const float4*)(Ablk + (size_t)row * K + k0 + acol);
            As[acol + 0][row] = a.x;
            As[acol + 1][row] = a.y;
            As[acol + 2][row] = a.z;
            As[acol + 3][row] = a.w;
        }
        #pragma unroll
        for (int r = 0; r < 2; r++) {
            int krow = brow + r * 8;
            *(float4*)&Bs[krow][bcol] =
                *(const float4*)(Bblk + (size_t)(k0 + krow) * N + bcol);
        }
        __syncthreads();

        #pragma unroll
        for (int kk = 0; kk < BK; kk++) {
            float ra[TM], rb[TNt];
            #pragma unroll
            for (int i = 0; i < TM; i++) ra[i] = As[kk][ty * TM + i];
            #pragma unroll
            for (int j = 0; j < TNt; j++) rb[j] = Bs[kk][tx * TNt + j];
            #pragma unroll
            for (int i = 0; i < TM; i++)
                #pragma unroll
                for (int j = 0; j < TNt; j++)
                    acc[i][j] = fmaf(ra[i], rb[j], acc[i][j]);
        }
        __syncthreads();
    }

    float bvals[TNt];
    #pragma unroll
    for (int j = 0; j < TNt; j++)
        bvals[j] = bias ? bias[bx * BN + tx * TNt + j] : 0.0f;

    #pragma unroll
    for (int i = 0; i < TM; i++) {
        int row = by * BM + ty * TM + i;
        float* Crow = C + (size_t)row * N + bx * BN + tx * TNt;
        #pragma unroll
        for (int j = 0; j < TNt; j++)
            Crow[j] = acc[i][j] + bvals[j];
    }
}

// C[M,N] = scale * (A[M,K] @ B[N,K]^T).  Both operands K-contiguous (TN).
__global__ __launch_bounds__(256, 2)
void gemm_tn_scaled(const float* __restrict__ A, const float* __restrict__ B,
                    float* __restrict__ C, int M, int N, int K, float scale)
{
    __shared__ float As[BK][BM];
    __shared__ float Bs[BK][BN];

    const int bx = blockIdx.x;            // N tile (rows of B)
    const int by = blockIdx.y;            // M tile
    const int tid = threadIdx.x;
    const int tx = tid & 15;
    const int ty = tid >> 4;

    const float* Ablk = A + (size_t)by * BM * K;
    const float* Bblk = B + (size_t)bx * BN * K;

    const int lrow = tid >> 2;            // 0..63 (+64)
    const int lcol = (tid & 3) * 4;       // k offset

    float acc[TM][TNt];
    #pragma unroll
    for (int i = 0; i < TM; i++)
        #pragma unroll
        for (int j = 0; j < TNt; j++) acc[i][j] = 0.0f;

    for (int k0 = 0; k0 < K; k0 += BK) {
        #pragma unroll
        for (int r = 0; r < 2; r++) {
            int row = lrow + r * 64;
            float4 a = *(const float4*)(Ablk + (size_t)row * K + k0 + lcol);
            As[lcol + 0][row] = a.x;
            As[lcol + 1][row] = a.y;
            As[lcol + 2][row] = a.z;
            As[lcol + 3][row] = a.w;
            float4 b = *(const float4*)(Bblk + (size_t)row * K + k0 + lcol);
            Bs[lcol + 0][row] = b.x;
            Bs[lcol + 1][row] = b.y;
            Bs[lcol + 2][row] = b.z;
            Bs[lcol + 3][row] = b.w;
        }
        __syncthreads();

        #pragma unroll
        for (int kk = 0; kk < BK; kk++) {
            float ra[TM], rb[TNt];
            #pragma unroll
            for (int i = 0; i < TM; i++) ra[i] = As[kk][ty * TM + i];
            #pragma unroll
            for (int j = 0; j < TNt; j++) rb[j] = Bs[kk][tx * TNt + j];
            #pragma unroll
            for (int i = 0; i < TM; i++)
                #pragma unroll
                for (int j = 0; j < TNt; j++)
                    acc[i][j] = fmaf(ra[i], rb[j], acc[i][j]);
        }
        __syncthreads();
    }

    #pragma unroll
    for (int i = 0; i < TM; i++) {
        int row = by * BM + ty * TM + i;
        float* Crow = C + (size_t)row * N + bx * BN + tx * TNt;
        #pragma unroll
        for (int j = 0; j < TNt; j++)
            Crow[j] = acc[i][j] * scale;
    }
}

// ---------------------------------------------------------------------------
// Row softmax over 4096 columns; one block (256 threads) per row.
// Each thread holds exactly 16 elements in registers: one read + one write.
// ---------------------------------------------------------------------------
__global__ __launch_bounds__(256)
void softmax_rows(float* __restrict__ S)
{
    const int row = blockIdx.x;
    float* p = S + (size_t)row * CCTX;
    const int t = threadIdx.x;
    const int lane = t & 31;
    const int warp = t >> 5;
    __shared__ float red[8];

    float vals[16];
    float mx = -INFINITY;
    #pragma unroll
    for (int i = 0; i < 16; i++) {
        vals[i] = p[t + i * 256];
        mx = fmaxf(mx, vals[i]);
    }
    #pragma unroll
    for (int o = 16; o > 0; o >>= 1)
        mx = fmaxf(mx, __shfl_xor_sync(0xffffffffu, mx, o));
    if (lane == 0) red[warp] = mx;
    __syncthreads();
    float m = red[0];
    #pragma unroll
    for (int w = 1; w < 8; w++) m = fmaxf(m, red[w]);
    __syncthreads();

    float sum = 0.0f;
    #pragma unroll
    for (int i = 0; i < 16; i++) {
        vals[i] = __expf(vals[i] - m);
        sum += vals[i];
    }
    #pragma unroll
    for (int o = 16; o > 0; o >>= 1)
        sum += __shfl_xor_sync(0xffffffffu, sum, o);
    if (lane == 0) red[warp] = sum;
    __syncthreads();
    float s = red[0];
    #pragma unroll
    for (int w = 1; w < 8; w++) s += red[w];

    float inv = 1.0f / s;
    #pragma unroll
    for (int i = 0; i < 16; i++)
        p[t + i * 256] = vals[i] * inv;
}

// ---------------------------------------------------------------------------
// Launch
// ---------------------------------------------------------------------------
extern "C" void kernel_launch(void* const* d_in, const int* in_sizes, int n_in,
                              void* d_out, int out_size)
{
    const float* model = (const float*)d_in[0];   // [16,1024,512]
    const float* ctx   = (const float*)d_in[1];   // [4096,512]
    const float* Wq    = (const float*)d_in[2];
    const float* bq    = (const float*)d_in[3];
    const float* Wk    = (const float*)d_in[4];
    const float* bk    = (const float*)d_in[5];
    const float* Wv    = (const float*)d_in[6];
    const float* bv    = (const float*)d_in[7];
    const float* Wo    = (const float*)d_in[8];
    const float* bo    = (const float*)d_in[9];
    float* out = (float*)d_out;                   // [16,1024,512] fp32

    float *q, *k, *v, *s, *x;
    cudaGetSymbolAddress((void**)&q, g_q);
    cudaGetSymbolAddress((void**)&k, g_k);
    cudaGetSymbolAddress((void**)&v, g_v);
    cudaGetSymbolAddress((void**)&s, g_s);
    cudaGetSymbolAddress((void**)&x, g_x);

    const dim3 blk(256);

    // q = model @ Wq + bq            [16384,512]
    gemm_nn_bias<<<dim3(DMOD / BN, M_Q / BM), blk>>>(model, Wq, bq, q, M_Q, DMOD, DMOD);
    // k = ctx @ Wk + bk              [4096,512]
    gemm_nn_bias<<<dim3(DMOD / BN, CCTX / BM), blk>>>(ctx, Wk, bk, k, CCTX, DMOD, DMOD);
    // v = ctx @ Wv + bv              [4096,512]
    gemm_nn_bias<<<dim3(DMOD / BN, CCTX / BM), blk>>>(ctx, Wv, bv, v, CCTX, DMOD, DMOD);
    // scores = scale * q @ k^T       [16384,4096]
    gemm_tn_scaled<<<dim3(CCTX / BN, M_Q / BM), blk>>>(q, k, s, M_Q, CCTX, DMOD, SCALE_A);
    // softmax over context dim (in place)
    softmax_rows<<<M_Q, blk>>>(s);
    // x = attn @ v                   [16384,512]
    gemm_nn_bias<<<dim3(DMOD / BN, M_Q / BM), blk>>>(s, v, nullptr, x, M_Q, DMOD, CCTX);
    // out = x @ Wo + bo              [16384,512]
    gemm_nn_bias<<<dim3(DMOD / BN, M_Q / BM), blk>>>(x, Wo, bo, out, M_Q, DMOD, DMOD);
}